// round 1
// baseline (speedup 1.0000x reference)
#include <cuda_runtime.h>

#define BB 64
#define NN 4096
#define FF 128
#define DD 129
#define EPSV 1e-7f

// Scratch (no allocations allowed) — re-zeroed every launch by zero_kernel.
__device__ float g_s[BB * DD];       // per-batch sums
__device__ float g_mu[BB * DD];      // Lorentz centroid per batch
__device__ float g_bm[DD];           // bias point on manifold
__device__ float g_alpha[BB * NN];   // per-point alpha cache
__device__ float g_varsum[BB];       // sum of squared geodesic distances
__device__ float g_c[BB];            // sqrt(weight/(var+1e-6))
__device__ float g_kdi[BB];          // 1/(1 - ldot(mu, bias_m))

__global__ void zero_kernel() {
    int i = blockIdx.x * blockDim.x + threadIdx.x;
    if (i < BB * DD) g_s[i] = 0.f;
    if (i < BB) g_varsum[i] = 0.f;
}

// Pass 1: s[b][d] = sum_n x[b,n,d]. Grid (8 slices, B). Block = 516 = 4*129.
// Thread tid always reads component d = tid % 129 (stride 516 = 4 rows),
// fully coalesced.
__global__ void sum_kernel(const float* __restrict__ x) {
    __shared__ float sh[516];
    int b = blockIdx.y, s = blockIdx.x, tid = threadIdx.x;
    const float* p = x + (size_t)b * NN * DD + (size_t)s * 512 * DD + tid;
    float acc = 0.f;
#pragma unroll 8
    for (int i = 0; i < 128; i++) acc += p[(size_t)i * 516];
    sh[tid] = acc;
    __syncthreads();
    if (tid < DD) {
        float t = sh[tid] + sh[tid + 129] + sh[tid + 258] + sh[tid + 387];
        atomicAdd(&g_s[b * DD + tid], t);
    }
}

__device__ __forceinline__ float block_reduce256(float v, float* sh) {
    int t = threadIdx.x;
    sh[t] = v;
    __syncthreads();
    for (int s = 128; s > 0; s >>= 1) {
        if (t < s) sh[t] += sh[t + s];
        __syncthreads();
    }
    float r = sh[0];
    __syncthreads();
    return r;
}

// Blocks 0..63: mu[b] = s / sqrt(max(-ldot(s,s), EPS)).
// Block 64: bias_m = expmap(origin, [0, bias]).
__global__ void mu_kernel(const float* __restrict__ bias) {
    __shared__ float sh[256];
    int b = blockIdx.x, t = threadIdx.x;
    if (b < BB) {
        float sv = (t < DD) ? g_s[b * DD + t] : 0.f;
        float val = (t == 0) ? sv * sv : -sv * sv;  // -ldot(s,s) contribution
        if (t >= DD) val = 0.f;
        float r = block_reduce256(val, sh);
        float inv = rsqrtf(fmaxf(r, EPSV));
        if (t < DD) g_mu[b * DD + t] = sv * inv;
    } else {
        float bv = (t < FF) ? bias[t] : 0.f;
        float r = block_reduce256(bv * bv, sh);  // ldot(v,v) with v=[0,bias]
        float n = sqrtf(fmaxf(r, EPSV));
        float scl = sinhf(n) / n;
        if (t < FF) g_bm[1 + t] = scl * bv;
        if (t == 0) g_bm[0] = coshf(n);
    }
}

// Pass 2: alpha[b,n] = max(-ldot(mu, x), 1+EPS); varsum[b] += arccosh(alpha)^2.
// One warp per point, 8 warps/block, all warps in a block share batch b.
__global__ void var_kernel(const float* __restrict__ x) {
    __shared__ float shmu[DD];
    __shared__ float ssum;
    int b = blockIdx.y, t = threadIdx.x;
    if (t < DD) shmu[t] = g_mu[b * DD + t];
    if (t == 0) ssum = 0.f;
    __syncthreads();
    int warp = t >> 5, lane = t & 31;
    int n = blockIdx.x * 8 + warp;
    const float* p = x + ((size_t)b * NN + n) * DD;
    // -ldot(mu,x) = mu0*x0 - sum_{i>=1} mu_i*x_i
    float acc = 0.f;
#pragma unroll
    for (int k = 0; k < 4; k++) {
        int idx = lane + 32 * k;
        float c = p[idx] * shmu[idx];
        acc += (idx == 0) ? c : -c;
    }
    if (lane == 0) acc -= p[128] * shmu[128];
#pragma unroll
    for (int o = 16; o > 0; o >>= 1) acc += __shfl_xor_sync(0xffffffffu, acc, o);
    if (lane == 0) {
        float alpha = fmaxf(acc, 1.f + EPSV);
        g_alpha[(size_t)b * NN + n] = alpha;
        float d = acoshf(alpha);
        atomicAdd(&ssum, d * d);
    }
    __syncthreads();
    if (t == 0) atomicAdd(&g_varsum[b], ssum);
}

// Per-batch scalars: kdi = 1/(1 - ldot(mu,bias_m)); c = sqrt(w/(var+1e-6)).
__global__ void scal_kernel(const float* __restrict__ weight) {
    __shared__ float sh[256];
    int b = blockIdx.x, t = threadIdx.x;
    float mv = (t < DD) ? g_mu[b * DD + t] : 0.f;
    float bm = (t < DD) ? g_bm[t] : 0.f;
    float val = (t == 0) ? -mv * bm : mv * bm;  // ldot(mu, bm)
    float ld = block_reduce256(val, sh);
    if (t == 0) {
        g_kdi[b] = 1.f / (1.f - ld);
        float var = g_varsum[b] / (float)NN;
        g_c[b] = sqrtf(weight[0] / (var + 1e-6f));
    }
}

// Pass 3: pointwise logmap -> transport -> scale -> expmap. One warp per point.
__global__ void out_kernel(const float* __restrict__ x, float* __restrict__ out) {
    __shared__ float shmu[DD], shbm[DD];
    __shared__ float sc, skdi;
    int b = blockIdx.y, t = threadIdx.x;
    if (t < DD) { shmu[t] = g_mu[b * DD + t]; shbm[t] = g_bm[t]; }
    if (t == 0) { sc = g_c[b]; skdi = g_kdi[b]; }
    __syncthreads();
    int warp = t >> 5, lane = t & 31;
    int n = blockIdx.x * 8 + warp;
    size_t base = ((size_t)b * NN + n) * DD;
    const float* p = x + base;
    float* o = out + base;

    float alpha = g_alpha[(size_t)b * NN + n];
    float d = acoshf(alpha);

    float u[4], mk[4], bk[4];
    float u4 = 0.f, m4 = 0.f, b4 = 0.f;
    float nu2 = 0.f, bdotu = 0.f;
#pragma unroll
    for (int k = 0; k < 4; k++) {
        int idx = lane + 32 * k;
        mk[k] = shmu[idx];
        bk[k] = shbm[idx];
        u[k] = p[idx] - alpha * mk[k];
        float sgn = (idx == 0) ? -1.f : 1.f;
        nu2 += sgn * u[k] * u[k];
        bdotu += sgn * bk[k] * u[k];
    }
    if (lane == 0) {
        m4 = shmu[128]; b4 = shbm[128];
        u4 = p[128] - alpha * m4;
        nu2 += u4 * u4;
        bdotu += b4 * u4;
    }
#pragma unroll
    for (int o2 = 16; o2 > 0; o2 >>= 1) {
        nu2 += __shfl_xor_sync(0xffffffffu, nu2, o2);
        bdotu += __shfl_xor_sync(0xffffffffu, bdotu, o2);
    }
    float nu = sqrtf(fmaxf(nu2, EPSV));
    float vs = d / nu;               // v = vs * u
    float kk = vs * bdotu * skdi;    // ldot(bm,v) / (1 - ldot(mu,bm))

    // vt = c * (v + kk*(mu + bm)); nn2 = ldot(vt, vt)
    float vt[4], vt4 = 0.f;
    float nn2 = 0.f;
#pragma unroll
    for (int k = 0; k < 4; k++) {
        int idx = lane + 32 * k;
        vt[k] = sc * (vs * u[k] + kk * (mk[k] + bk[k]));
        float sgn = (idx == 0) ? -1.f : 1.f;
        nn2 += sgn * vt[k] * vt[k];
    }
    if (lane == 0) {
        vt4 = sc * (vs * u4 + kk * (m4 + b4));
        nn2 += vt4 * vt4;
    }
#pragma unroll
    for (int o2 = 16; o2 > 0; o2 >>= 1) nn2 += __shfl_xor_sync(0xffffffffu, nn2, o2);

    float nn = sqrtf(fmaxf(nn2, EPSV));
    float ch = coshf(nn);
    float shn = sinhf(nn) / nn;
#pragma unroll
    for (int k = 0; k < 4; k++) {
        int idx = lane + 32 * k;
        o[idx] = ch * bk[k] + shn * vt[k];
    }
    if (lane == 0) o[128] = ch * b4 + shn * vt4;
}

extern "C" void kernel_launch(void* const* d_in, const int* in_sizes, int n_in,
                              void* d_out, int out_size) {
    const float* x = (const float*)d_in[0];
    const float* bias = (const float*)d_in[1];
    const float* weight = (const float*)d_in[2];
    float* out = (float*)d_out;

    zero_kernel<<<(BB * DD + 255) / 256, 256>>>();
    sum_kernel<<<dim3(8, BB), 516>>>(x);
    mu_kernel<<<65, 256>>>(bias);
    var_kernel<<<dim3(NN / 8, BB), 256>>>(x);
    scal_kernel<<<BB, 256>>>(weight);
    out_kernel<<<dim3(NN / 8, BB), 256>>>(x, out);
}

// round 2
// speedup vs baseline: 1.0688x; 1.0688x over previous
#include <cuda_runtime.h>

#define BB 64
#define NN 4096
#define FF 128
#define DD 129
#define EPSV 1e-7f
#define PTS 32            // points per block in var/out kernels
#define TILE_F4 (PTS * DD / 4 + (PTS * DD % 4 ? 1 : 0))  // 1032 float4 (exact: 32*129=4128/4)

__device__ float g_spart[8 * BB * DD]; // per-slice partial sums
__device__ float g_mu[BB * DD];        // Lorentz centroid per batch
__device__ float g_bm[DD];             // bias point on manifold
__device__ float g_alpha[BB * NN];     // per-point alpha cache
__device__ float g_varsum[BB];         // sum of squared geodesic distances
__device__ float g_c[BB];              // sqrt(weight/(var+1e-6))
__device__ float g_kdi[BB];            // 1/(1 - ldot(mu, bias_m))

// Pass 1: partial sums over n, vectorized. Grid (8 slices, B), block 516.
// A 16-row group = 16*129 = 2064 floats = 516 float4. Thread t always loads
// float4 #t of each group -> fixed components (4t+j) mod 129.
__global__ void sum_kernel(const float* __restrict__ x) {
    __shared__ float sh[2064];
    int b = blockIdx.y, s = blockIdx.x, t = threadIdx.x;
    const float4* p = (const float4*)(x + (size_t)b * NN * DD + (size_t)s * 512 * DD);
    float a0 = 0.f, a1 = 0.f, a2 = 0.f, a3 = 0.f;
#pragma unroll 4
    for (int g = 0; g < 32; g++) {
        float4 v = p[(size_t)g * 516 + t];
        a0 += v.x; a1 += v.y; a2 += v.z; a3 += v.w;
    }
    sh[4 * t + 0] = a0; sh[4 * t + 1] = a1; sh[4 * t + 2] = a2; sh[4 * t + 3] = a3;
    __syncthreads();
    if (t < DD) {
        float acc = 0.f;
#pragma unroll
        for (int r = 0; r < 16; r++) acc += sh[t + DD * r];
        g_spart[(s * BB + b) * DD + t] = acc;
    }
}

__device__ __forceinline__ float block_reduce256(float v, float* sh) {
    int t = threadIdx.x;
    sh[t] = v;
    __syncthreads();
    for (int s = 128; s > 0; s >>= 1) {
        if (t < s) sh[t] += sh[t + s];
        __syncthreads();
    }
    float r = sh[0];
    __syncthreads();
    return r;
}

// Blocks 0..63: mu[b] = s / sqrt(max(-ldot(s,s), EPS)); also zero varsum.
// Block 64: bias_m = expmap(origin, [0, bias]).
__global__ void mu_kernel(const float* __restrict__ bias) {
    __shared__ float sh[256];
    int b = blockIdx.x, t = threadIdx.x;
    if (b < BB) {
        float sv = 0.f;
        if (t < DD) {
#pragma unroll
            for (int s = 0; s < 8; s++) sv += g_spart[(s * BB + b) * DD + t];
        }
        float val = (t == 0) ? sv * sv : -sv * sv;  // -ldot(s,s)
        if (t >= DD) val = 0.f;
        float r = block_reduce256(val, sh);
        float inv = rsqrtf(fmaxf(r, EPSV));
        if (t < DD) g_mu[b * DD + t] = sv * inv;
        if (t == 0) g_varsum[b] = 0.f;
    } else {
        float bv = (t < FF) ? bias[t] : 0.f;
        float r = block_reduce256(bv * bv, sh);
        float n = sqrtf(fmaxf(r, EPSV));
        float scl = sinhf(n) / n;
        if (t < FF) g_bm[1 + t] = scl * bv;
        if (t == 0) g_bm[0] = coshf(n);
    }
}

// Pass 2: stage 32 points via float4 into SMEM, warp-reduce alpha, accumulate var.
__global__ void var_kernel(const float* __restrict__ x) {
    __shared__ float sx[PTS * DD];   // 16512 B
    __shared__ float shmu[DD];
    __shared__ float ssum;
    int b = blockIdx.y, t = threadIdx.x;
    int n0 = blockIdx.x * PTS;
    if (t < DD) shmu[t] = g_mu[b * DD + t];
    if (t == 0) ssum = 0.f;
    const float4* src = (const float4*)(x + ((size_t)b * NN + n0) * DD);
    float4* dst = (float4*)sx;
    for (int i = t; i < 1032; i += 256) dst[i] = src[i];
    __syncthreads();

    int warp = t >> 5, lane = t & 31;
    float lsum = 0.f;
#pragma unroll
    for (int pp = 0; pp < 4; pp++) {
        int nl = warp * 4 + pp;
        const float* p = sx + nl * DD;
        float acc = 0.f;
#pragma unroll
        for (int k = 0; k < 4; k++) {
            int idx = lane + 32 * k;
            float c = p[idx] * shmu[idx];
            acc += (idx == 0) ? c : -c;
        }
        if (lane == 0) acc -= p[128] * shmu[128];
#pragma unroll
        for (int o = 16; o > 0; o >>= 1) acc += __shfl_xor_sync(0xffffffffu, acc, o);
        if (lane == 0) {
            float alpha = fmaxf(acc, 1.f + EPSV);
            g_alpha[(size_t)b * NN + n0 + nl] = alpha;
            float d = acoshf(alpha);
            lsum += d * d;
        }
    }
    if (lane == 0) atomicAdd(&ssum, lsum);
    __syncthreads();
    if (t == 0) atomicAdd(&g_varsum[b], ssum);
}

// Per-batch scalars.
__global__ void scal_kernel(const float* __restrict__ weight) {
    __shared__ float sh[256];
    int b = blockIdx.x, t = threadIdx.x;
    float mv = (t < DD) ? g_mu[b * DD + t] : 0.f;
    float bm = (t < DD) ? g_bm[t] : 0.f;
    float val = (t == 0) ? -mv * bm : mv * bm;  // ldot(mu, bm)
    float ld = block_reduce256(val, sh);
    if (t == 0) {
        g_kdi[b] = 1.f / (1.f - ld);
        float var = g_varsum[b] / (float)NN;
        g_c[b] = sqrtf(weight[0] / (var + 1e-6f));
    }
}

// Pass 3: stage tile, compute logmap->transport->scale->expmap in place, flush.
__global__ void out_kernel(const float* __restrict__ x, float* __restrict__ out) {
    __shared__ float sx[PTS * DD];
    __shared__ float shmu[DD], shbm[DD];
    __shared__ float sc, skdi;
    int b = blockIdx.y, t = threadIdx.x;
    int n0 = blockIdx.x * PTS;
    if (t < DD) { shmu[t] = g_mu[b * DD + t]; shbm[t] = g_bm[t]; }
    if (t == 0) { sc = g_c[b]; skdi = g_kdi[b]; }
    size_t base = ((size_t)b * NN + n0) * DD;
    const float4* src = (const float4*)(x + base);
    float4* dst = (float4*)sx;
    for (int i = t; i < 1032; i += 256) dst[i] = src[i];
    __syncthreads();

    int warp = t >> 5, lane = t & 31;
#pragma unroll
    for (int pp = 0; pp < 4; pp++) {
        int nl = warp * 4 + pp;
        float* p = sx + nl * DD;
        float alpha = g_alpha[(size_t)b * NN + n0 + nl];
        float d = acoshf(alpha);

        float u[4], mk[4], bk[4];
        float u4 = 0.f, m4 = 0.f, b4 = 0.f;
        float nu2 = 0.f, bdotu = 0.f;
#pragma unroll
        for (int k = 0; k < 4; k++) {
            int idx = lane + 32 * k;
            mk[k] = shmu[idx];
            bk[k] = shbm[idx];
            u[k] = p[idx] - alpha * mk[k];
            float sgn = (idx == 0) ? -1.f : 1.f;
            nu2 += sgn * u[k] * u[k];
            bdotu += sgn * bk[k] * u[k];
        }
        if (lane == 0) {
            m4 = shmu[128]; b4 = shbm[128];
            u4 = p[128] - alpha * m4;
            nu2 += u4 * u4;
            bdotu += b4 * u4;
        }
#pragma unroll
        for (int o = 16; o > 0; o >>= 1) {
            nu2 += __shfl_xor_sync(0xffffffffu, nu2, o);
            bdotu += __shfl_xor_sync(0xffffffffu, bdotu, o);
        }
        float nu = sqrtf(fmaxf(nu2, EPSV));
        float vs = d / nu;
        float kk = vs * bdotu * skdi;

        float vt[4], vt4 = 0.f;
        float nn2 = 0.f;
#pragma unroll
        for (int k = 0; k < 4; k++) {
            int idx = lane + 32 * k;
            vt[k] = sc * (vs * u[k] + kk * (mk[k] + bk[k]));
            float sgn = (idx == 0) ? -1.f : 1.f;
            nn2 += sgn * vt[k] * vt[k];
        }
        if (lane == 0) {
            vt4 = sc * (vs * u4 + kk * (m4 + b4));
            nn2 += vt4 * vt4;
        }
#pragma unroll
        for (int o = 16; o > 0; o >>= 1) nn2 += __shfl_xor_sync(0xffffffffu, nn2, o);

        float nn = sqrtf(fmaxf(nn2, EPSV));
        float ch = coshf(nn);
        float shn = sinhf(nn) / nn;
#pragma unroll
        for (int k = 0; k < 4; k++) {
            int idx = lane + 32 * k;
            p[idx] = ch * bk[k] + shn * vt[k];
        }
        if (lane == 0) p[128] = ch * b4 + shn * vt4;
    }
    __syncthreads();
    float4* odst = (float4*)(out + base);
    for (int i = t; i < 1032; i += 256) odst[i] = dst[i];
}

extern "C" void kernel_launch(void* const* d_in, const int* in_sizes, int n_in,
                              void* d_out, int out_size) {
    const float* x = (const float*)d_in[0];
    const float* bias = (const float*)d_in[1];
    const float* weight = (const float*)d_in[2];
    float* out = (float*)d_out;

    sum_kernel<<<dim3(8, BB), 516>>>(x);
    mu_kernel<<<65, 256>>>(bias);
    var_kernel<<<dim3(NN / PTS, BB), 256>>>(x);
    scal_kernel<<<BB, 256>>>(weight);
    out_kernel<<<dim3(NN / PTS, BB), 256>>>(x, out);
}

// round 3
// speedup vs baseline: 1.3145x; 1.2299x over previous
#include <cuda_runtime.h>

#define BB 64
#define NN 4096
#define FF 128
#define DD 129
#define EPSV 1e-7f

__device__ float g_spart[8 * BB * DD];
__device__ float g_mu[BB * DD];
__device__ float g_bm[DD];
__device__ float g_a[BB * NN];     // unclamped -ldot(mu,x)
__device__ float g_beta[BB * NN];  // ldot(bm,x)
__device__ float g_nu2[BB * NN];   // ldot(u,u) raw
__device__ float g_cx[BB * NN];
__device__ float g_cm[BB * NN];
__device__ float g_cb[BB * NN];
__device__ float g_varsum[BB];

// Pass 1: partial sums over n. Grid (8, B), block 516.
__global__ void sum_kernel(const float* __restrict__ x) {
    __shared__ float sh[2064];
    int b = blockIdx.y, s = blockIdx.x, t = threadIdx.x;
    const float4* p = (const float4*)(x + (size_t)b * NN * DD + (size_t)s * 512 * DD);
    float a0 = 0.f, a1 = 0.f, a2 = 0.f, a3 = 0.f;
#pragma unroll 4
    for (int g = 0; g < 32; g++) {
        float4 v = p[(size_t)g * 516 + t];
        a0 += v.x; a1 += v.y; a2 += v.z; a3 += v.w;
    }
    sh[4 * t + 0] = a0; sh[4 * t + 1] = a1; sh[4 * t + 2] = a2; sh[4 * t + 3] = a3;
    __syncthreads();
    if (t < DD) {
        float acc = 0.f;
#pragma unroll
        for (int r = 0; r < 16; r++) acc += sh[t + DD * r];
        g_spart[(s * BB + b) * DD + t] = acc;
    }
}

__device__ __forceinline__ float block_reduce256(float v, float* sh) {
    int t = threadIdx.x;
    sh[t] = v;
    __syncthreads();
    for (int s = 128; s > 0; s >>= 1) {
        if (t < s) sh[t] += sh[t + s];
        __syncthreads();
    }
    float r = sh[0];
    __syncthreads();
    return r;
}

// Blocks 0..63: mu[b]; zero varsum. Block 64: bias_m.
__global__ void mu_kernel(const float* __restrict__ bias) {
    __shared__ float sh[256];
    int b = blockIdx.x, t = threadIdx.x;
    if (b < BB) {
        float sv = 0.f;
        if (t < DD) {
#pragma unroll
            for (int s = 0; s < 8; s++) sv += g_spart[(s * BB + b) * DD + t];
        }
        float val = (t == 0) ? sv * sv : -sv * sv;
        if (t >= DD) val = 0.f;
        float r = block_reduce256(val, sh);
        float inv = rsqrtf(fmaxf(r, EPSV));
        if (t < DD) g_mu[b * DD + t] = sv * inv;
        if (t == 0) g_varsum[b] = 0.f;
    } else {
        float bv = (t < FF) ? bias[t] : 0.f;
        float r = block_reduce256(bv * bv, sh);
        float n = sqrtf(fmaxf(r, EPSV));
        float scl = sinhf(n) / n;
        if (t < FF) g_bm[1 + t] = scl * bv;
        if (t == 0) g_bm[0] = coshf(n);
    }
}

// Pass 2: per-point a, beta, nu2 + varsum. Warp handles 4-point groups with
// register-resident mu/bm. Grid (16, BB) REVERSED for L2 reuse of pass 1.
__global__ __launch_bounds__(256) void var_kernel(const float* __restrict__ x) {
    __shared__ float smu[DD], sbm[DD];
    __shared__ float ssum;
    int t = threadIdx.x;
    int b = BB - 1 - blockIdx.y;
    int pbase = (15 - blockIdx.x) * 256;
    if (t < DD) { smu[t] = g_mu[b * DD + t]; sbm[t] = g_bm[t]; }
    if (t == 0) ssum = 0.f;
    __syncthreads();
    int w = t >> 5, l = t & 31;
    float mu_r[7], bm_r[7], mu_e[4], bm_e[4];
#pragma unroll
    for (int i = 0; i < 7; i++) {
        int c = 4 * l - 3 + i;
        mu_r[i] = (c >= 0) ? smu[c] : 0.f;
        bm_r[i] = (c >= 0) ? sbm[c] : 0.f;
    }
#pragma unroll
    for (int i = 0; i < 4; i++) { mu_e[i] = smu[125 + i]; bm_e[i] = sbm[125 + i]; }

    float vloc = 0.f;
    for (int g = w; g < 64; g += 8) {
        int n0 = pbase + g * 4;
        const float4* p4 = (const float4*)(x + ((size_t)b * NN + n0) * DD);
        float xr[4][4], xe[4];
#pragma unroll
        for (int k = 0; k < 4; k++) {
            float4 v = p4[l + 32 * k];
            xr[k][0] = v.x; xr[k][1] = v.y; xr[k][2] = v.z; xr[k][3] = v.w;
        }
        {
            float4 v = p4[128];  // only lane 0's value is used
            xe[0] = v.x; xe[1] = v.y; xe[2] = v.z; xe[3] = v.w;
        }
        float pa[4] = {0, 0, 0, 0}, pb[4] = {0, 0, 0, 0};
#pragma unroll
        for (int k = 0; k < 4; k++) {
#pragma unroll
            for (int j = 0; j < 4; j++) {
                float xv = xr[k][j];
                if (l == 0 && j < k) {
                    int i = 4 - k + j;  // comp 129-k+j -> mu_e index (129-k+j-125)
                    pa[k - 1 < 0 ? 0 : k - 1] -= mu_e[i] * xv;
                    pb[k - 1 < 0 ? 0 : k - 1] += bm_e[i] * xv;
                } else {
                    int c = 4 * l + j - k, i = j - k + 3;
                    float m = mu_r[i], bv = bm_r[i];
                    if (c == 0) { pa[k] += m * xv; pb[k] -= bv * xv; }
                    else        { pa[k] -= m * xv; pb[k] += bv * xv; }
                }
            }
        }
        if (l == 0) {
#pragma unroll
            for (int j = 0; j < 4; j++) { pa[3] -= mu_e[j] * xe[j]; pb[3] += bm_e[j] * xe[j]; }
        }
#pragma unroll
        for (int k = 0; k < 4; k++) {
#pragma unroll
            for (int o = 16; o > 0; o >>= 1) {
                pa[k] += __shfl_xor_sync(0xffffffffu, pa[k], o);
                pb[k] += __shfl_xor_sync(0xffffffffu, pb[k], o);
            }
        }
        float alpha[4];
#pragma unroll
        for (int k = 0; k < 4; k++) alpha[k] = fmaxf(pa[k], 1.f + EPSV);
        float pn[4] = {0, 0, 0, 0};
#pragma unroll
        for (int k = 0; k < 4; k++) {
#pragma unroll
            for (int j = 0; j < 4; j++) {
                float xv = xr[k][j];
                if (l == 0 && j < k) {
                    int i = 4 - k + j, n = k - 1 < 0 ? 0 : k - 1;
                    float u = xv - alpha[n] * mu_e[i];
                    pn[n] += u * u;
                } else {
                    int c = 4 * l + j - k, i = j - k + 3;
                    float u = xv - alpha[k] * mu_r[i];
                    pn[k] += (c == 0) ? -u * u : u * u;
                }
            }
        }
        if (l == 0) {
#pragma unroll
            for (int j = 0; j < 4; j++) {
                float u = xe[j] - alpha[3] * mu_e[j];
                pn[3] += u * u;
            }
        }
#pragma unroll
        for (int k = 0; k < 4; k++)
#pragma unroll
            for (int o = 16; o > 0; o >>= 1) pn[k] += __shfl_xor_sync(0xffffffffu, pn[k], o);
        if (l == 0) {
            size_t np = (size_t)b * NN + n0;
            *(float4*)(g_a + np) = make_float4(pa[0], pa[1], pa[2], pa[3]);
            *(float4*)(g_beta + np) = make_float4(pb[0], pb[1], pb[2], pb[3]);
            *(float4*)(g_nu2 + np) = make_float4(pn[0], pn[1], pn[2], pn[3]);
            float s = 0.f;
#pragma unroll
            for (int k = 0; k < 4; k++) { float d = acoshf(alpha[k]); s += d * d; }
            vloc += s;
        }
    }
    if (l == 0) atomicAdd(&ssum, vloc);
    __syncthreads();
    if (t == 0) atomicAdd(&g_varsum[b], ssum);
}

// Per-point output coefficients (fused per-batch scalar computation).
__global__ void coef_kernel(const float* __restrict__ weight) {
    __shared__ float sh[256];
    int b = blockIdx.y, bx = blockIdx.x, t = threadIdx.x;
    float mv = (t < DD) ? g_mu[b * DD + t] : 0.f;
    float bv = (t < DD) ? g_bm[t] : 0.f;
    float mm = block_reduce256((t == 0) ? -mv * mv : mv * mv, sh);  // ldot(mu,mu)
    float mb = block_reduce256((t == 0) ? -mv * bv : mv * bv, sh);  // ldot(mu,bm)
    float bb = block_reduce256((t == 0) ? -bv * bv : bv * bv, sh);  // ldot(bm,bm)
    float kdi = 1.f / (1.f - mb);
    float var = g_varsum[b] / (float)NN;
    float sc = sqrtf(weight[0] / (var + 1e-6f));
    float ww = mm + 2.f * mb + bb;

    size_t np = (size_t)b * NN + bx * 256 + t;
    float a = g_a[np], beta = g_beta[np], nu2 = g_nu2[np];
    float alpha = fmaxf(a, 1.f + EPSV);
    float d = acoshf(alpha);
    float nu = sqrtf(fmaxf(nu2, EPSV));
    float vs = d / nu;
    float lbu = beta - alpha * mb;        // ldot(bm,u)
    float q = vs * lbu * kdi;
    float udot = (-a - alpha * mm) + lbu; // ldot(u, mu+bm)
    float nn2 = sc * sc * (vs * vs * nu2 + 2.f * vs * q * udot + q * q * ww);
    float nn = sqrtf(fmaxf(nn2, EPSV));
    float ch = coshf(nn), shn = sinhf(nn) / nn;
    g_cx[np] = shn * sc * vs;
    g_cm[np] = shn * sc * (q - vs * alpha);
    g_cb[np] = ch + shn * sc * q;
}

// Pass 3: pure elementwise streaming. Grid (16, BB) forward.
__global__ __launch_bounds__(256) void out_kernel(const float* __restrict__ x,
                                                  float* __restrict__ out) {
    __shared__ float smu[DD], sbm[DD];
    int t = threadIdx.x;
    int b = blockIdx.y;
    int pbase = blockIdx.x * 256;
    if (t < DD) { smu[t] = g_mu[b * DD + t]; sbm[t] = g_bm[t]; }
    __syncthreads();
    int w = t >> 5, l = t & 31;
    float mu_r[7], bm_r[7], mu_e[4], bm_e[4];
#pragma unroll
    for (int i = 0; i < 7; i++) {
        int c = 4 * l - 3 + i;
        mu_r[i] = (c >= 0) ? smu[c] : 0.f;
        bm_r[i] = (c >= 0) ? sbm[c] : 0.f;
    }
#pragma unroll
    for (int i = 0; i < 4; i++) { mu_e[i] = smu[125 + i]; bm_e[i] = sbm[125 + i]; }

    for (int g = w; g < 64; g += 8) {
        int n0 = pbase + g * 4;
        size_t base = ((size_t)b * NN + n0) * DD;
        const float4* p4 = (const float4*)(x + base);
        float4* o4 = (float4*)(out + base);
        size_t np = (size_t)b * NN + n0;
        float4 cxv = *(const float4*)(g_cx + np);
        float4 cmv = *(const float4*)(g_cm + np);
        float4 cbv = *(const float4*)(g_cb + np);
        float cx[4] = {cxv.x, cxv.y, cxv.z, cxv.w};
        float cm[4] = {cmv.x, cmv.y, cmv.z, cmv.w};
        float cb[4] = {cbv.x, cbv.y, cbv.z, cbv.w};
#pragma unroll
        for (int k = 0; k < 4; k++) {
            float4 v = p4[l + 32 * k];
            float xr[4] = {v.x, v.y, v.z, v.w};
            float orr[4];
#pragma unroll
            for (int j = 0; j < 4; j++) {
                if (l == 0 && j < k) {
                    int i = 4 - k + j, n = k - 1 < 0 ? 0 : k - 1;
                    orr[j] = cx[n] * xr[j] + cm[n] * mu_e[i] + cb[n] * bm_e[i];
                } else {
                    int i = j - k + 3;
                    orr[j] = cx[k] * xr[j] + cm[k] * mu_r[i] + cb[k] * bm_r[i];
                }
            }
            o4[l + 32 * k] = make_float4(orr[0], orr[1], orr[2], orr[3]);
        }
        if (l == 0) {
            float4 v = p4[128];
            float xr[4] = {v.x, v.y, v.z, v.w};
            float orr[4];
#pragma unroll
            for (int j = 0; j < 4; j++)
                orr[j] = cx[3] * xr[j] + cm[3] * mu_e[j] + cb[3] * bm_e[j];
            o4[128] = make_float4(orr[0], orr[1], orr[2], orr[3]);
        }
    }
}

extern "C" void kernel_launch(void* const* d_in, const int* in_sizes, int n_in,
                              void* d_out, int out_size) {
    const float* x = (const float*)d_in[0];
    const float* bias = (const float*)d_in[1];
    const float* weight = (const float*)d_in[2];
    float* out = (float*)d_out;

    sum_kernel<<<dim3(8, BB), 516>>>(x);
    mu_kernel<<<65, 256>>>(bias);
    var_kernel<<<dim3(16, BB), 256>>>(x);
    coef_kernel<<<dim3(16, BB), 256>>>(weight);
    out_kernel<<<dim3(16, BB), 256>>>(x, out);
}

// round 4
// speedup vs baseline: 1.3727x; 1.0443x over previous
#include <cuda_runtime.h>

#define BB 64
#define NN 4096
#define FF 128
#define DD 129
#define EPSV 1e-7f

__device__ float g_spart[8 * BB * DD];
__device__ float g_mu[BB * DD];
__device__ float g_bm[DD];
__device__ float g_a[BB * NN];     // unclamped -ldot(mu,x)
__device__ float g_beta[BB * NN];  // ldot(bm,x)
__device__ float g_varsum[BB];
__device__ float4 g_bs[BB];        // (mb, mm, kdi, sc)
__device__ float g_ww[BB];         // ldot(mu+bm, mu+bm)

// Pass 1: partial sums over n. Grid (8, B), block 516.
__global__ void sum_kernel(const float* __restrict__ x) {
    __shared__ float sh[2064];
    int b = blockIdx.y, s = blockIdx.x, t = threadIdx.x;
    const float4* p = (const float4*)(x + (size_t)b * NN * DD + (size_t)s * 512 * DD);
    float a0 = 0.f, a1 = 0.f, a2 = 0.f, a3 = 0.f;
#pragma unroll 4
    for (int g = 0; g < 32; g++) {
        float4 v = p[(size_t)g * 516 + t];
        a0 += v.x; a1 += v.y; a2 += v.z; a3 += v.w;
    }
    sh[4 * t + 0] = a0; sh[4 * t + 1] = a1; sh[4 * t + 2] = a2; sh[4 * t + 3] = a3;
    __syncthreads();
    if (t < DD) {
        float acc = 0.f;
#pragma unroll
        for (int r = 0; r < 16; r++) acc += sh[t + DD * r];
        g_spart[(s * BB + b) * DD + t] = acc;
    }
}

__device__ __forceinline__ float block_reduce256(float v, float* sh) {
    int t = threadIdx.x;
    sh[t] = v;
    __syncthreads();
    for (int s = 128; s > 0; s >>= 1) {
        if (t < s) sh[t] += sh[t + s];
        __syncthreads();
    }
    float r = sh[0];
    __syncthreads();
    return r;
}

// Blocks 0..63: mu[b]; zero varsum. Block 64: bias_m.
__global__ void mu_kernel(const float* __restrict__ bias) {
    __shared__ float sh[256];
    int b = blockIdx.x, t = threadIdx.x;
    if (b < BB) {
        float sv = 0.f;
        if (t < DD) {
#pragma unroll
            for (int s = 0; s < 8; s++) sv += g_spart[(s * BB + b) * DD + t];
        }
        float val = (t == 0) ? sv * sv : -sv * sv;
        if (t >= DD) val = 0.f;
        float r = block_reduce256(val, sh);
        float inv = rsqrtf(fmaxf(r, EPSV));
        if (t < DD) g_mu[b * DD + t] = sv * inv;
        if (t == 0) g_varsum[b] = 0.f;
    } else {
        float bv = (t < FF) ? bias[t] : 0.f;
        float r = block_reduce256(bv * bv, sh);
        float n = sqrtf(fmaxf(r, EPSV));
        float scl = sinhf(n) / n;
        if (t < FF) g_bm[1 + t] = scl * bv;
        if (t == 0) g_bm[0] = coshf(n);
    }
}

// Pass 2: per-point a, beta + varsum. Grid (16, BB) REVERSED for L2 reuse.
__global__ __launch_bounds__(256) void var_kernel(const float* __restrict__ x) {
    __shared__ float smu[DD], sbm[DD];
    __shared__ float ssum;
    int t = threadIdx.x;
    int b = BB - 1 - blockIdx.y;
    int pbase = (15 - blockIdx.x) * 256;
    if (t < DD) { smu[t] = g_mu[b * DD + t]; sbm[t] = g_bm[t]; }
    if (t == 0) ssum = 0.f;
    __syncthreads();
    int w = t >> 5, l = t & 31;
    float mu_r[7], bm_r[7], mu_e[4], bm_e[4];
#pragma unroll
    for (int i = 0; i < 7; i++) {
        int c = 4 * l - 3 + i;
        mu_r[i] = (c >= 0) ? smu[c] : 0.f;
        bm_r[i] = (c >= 0) ? sbm[c] : 0.f;
    }
#pragma unroll
    for (int i = 0; i < 4; i++) { mu_e[i] = smu[125 + i]; bm_e[i] = sbm[125 + i]; }

    float vloc = 0.f;
    for (int g = w; g < 64; g += 8) {
        int n0 = pbase + g * 4;
        const float4* p4 = (const float4*)(x + ((size_t)b * NN + n0) * DD);
        float xr[4][4], xe[4];
#pragma unroll
        for (int k = 0; k < 4; k++) {
            float4 v = p4[l + 32 * k];
            xr[k][0] = v.x; xr[k][1] = v.y; xr[k][2] = v.z; xr[k][3] = v.w;
        }
        {
            float4 v = p4[128];  // only lane 0's value is used
            xe[0] = v.x; xe[1] = v.y; xe[2] = v.z; xe[3] = v.w;
        }
        float pa[4] = {0, 0, 0, 0}, pb[4] = {0, 0, 0, 0};
#pragma unroll
        for (int k = 0; k < 4; k++) {
#pragma unroll
            for (int j = 0; j < 4; j++) {
                float xv = xr[k][j];
                if (l == 0 && j < k) {
                    int i = 4 - k + j;
                    pa[k - 1 < 0 ? 0 : k - 1] -= mu_e[i] * xv;
                    pb[k - 1 < 0 ? 0 : k - 1] += bm_e[i] * xv;
                } else {
                    int c = 4 * l + j - k, i = j - k + 3;
                    float m = mu_r[i], bv = bm_r[i];
                    if (c == 0) { pa[k] += m * xv; pb[k] -= bv * xv; }
                    else        { pa[k] -= m * xv; pb[k] += bv * xv; }
                }
            }
        }
        if (l == 0) {
#pragma unroll
            for (int j = 0; j < 4; j++) { pa[3] -= mu_e[j] * xe[j]; pb[3] += bm_e[j] * xe[j]; }
        }
#pragma unroll
        for (int k = 0; k < 4; k++) {
#pragma unroll
            for (int o = 16; o > 0; o >>= 1) {
                pa[k] += __shfl_xor_sync(0xffffffffu, pa[k], o);
                pb[k] += __shfl_xor_sync(0xffffffffu, pb[k], o);
            }
        }
        if (l == 0) {
            size_t np = (size_t)b * NN + n0;
            *(float4*)(g_a + np) = make_float4(pa[0], pa[1], pa[2], pa[3]);
            *(float4*)(g_beta + np) = make_float4(pb[0], pb[1], pb[2], pb[3]);
            float s = 0.f;
#pragma unroll
            for (int k = 0; k < 4; k++) {
                float alpha = fmaxf(pa[k], 1.f + EPSV);
                float d = acoshf(alpha);
                s += d * d;
            }
            vloc += s;
        }
    }
    if (l == 0) atomicAdd(&ssum, vloc);
    __syncthreads();
    if (t == 0) atomicAdd(&g_varsum[b], ssum);
}

// Per-batch scalars only (64 blocks).
__global__ void scal_kernel(const float* __restrict__ weight) {
    __shared__ float sh[256];
    int b = blockIdx.x, t = threadIdx.x;
    float mv = (t < DD) ? g_mu[b * DD + t] : 0.f;
    float bv = (t < DD) ? g_bm[t] : 0.f;
    float mm = block_reduce256((t == 0) ? -mv * mv : mv * mv, sh);
    float mb = block_reduce256((t == 0) ? -mv * bv : mv * bv, sh);
    float bb = block_reduce256((t == 0) ? -bv * bv : bv * bv, sh);
    if (t == 0) {
        float kdi = 1.f / (1.f - mb);
        float var = g_varsum[b] / (float)NN;
        float sc = sqrtf(weight[0] / (var + 1e-6f));
        g_bs[b] = make_float4(mb, mm, kdi, sc);
        g_ww[b] = mm + 2.f * mb + bb;
    }
}

// Pass 3: inline coefficients + elementwise streaming, evict-first stores.
__global__ __launch_bounds__(256) void out_kernel(const float* __restrict__ x,
                                                  float* __restrict__ out) {
    __shared__ float smu[DD], sbm[DD];
    __shared__ float4 sbs;
    __shared__ float sww;
    int t = threadIdx.x;
    int b = blockIdx.y;
    int pbase = blockIdx.x * 256;
    if (t < DD) { smu[t] = g_mu[b * DD + t]; sbm[t] = g_bm[t]; }
    if (t == 0) { sbs = g_bs[b]; sww = g_ww[b]; }
    __syncthreads();
    float mb = sbs.x, mm = sbs.y, kdi = sbs.z, sc = sbs.w, ww = sww;
    int w = t >> 5, l = t & 31;
    float mu_r[7], bm_r[7], mu_e[4], bm_e[4];
#pragma unroll
    for (int i = 0; i < 7; i++) {
        int c = 4 * l - 3 + i;
        mu_r[i] = (c >= 0) ? smu[c] : 0.f;
        bm_r[i] = (c >= 0) ? sbm[c] : 0.f;
    }
#pragma unroll
    for (int i = 0; i < 4; i++) { mu_e[i] = smu[125 + i]; bm_e[i] = sbm[125 + i]; }

    for (int g = w; g < 64; g += 8) {
        int n0 = pbase + g * 4;
        size_t base = ((size_t)b * NN + n0) * DD;
        const float4* p4 = (const float4*)(x + base);
        float4* o4 = (float4*)(out + base);
        size_t np = (size_t)b * NN + n0;

        // Lanes 0-3 own points 0-3; others replicate lane l&3 (in-bounds).
        int li = l & 3;
        float av = g_a[np + li];
        float betav = g_beta[np + li];
        float alpha = fmaxf(av, 1.f + EPSV);
        float d = acoshf(alpha);
        float nu2 = 2.f * alpha * av - alpha * alpha - 1.f;  // ldot(u,u) analytic
        float nu = sqrtf(fmaxf(nu2, EPSV));
        float vs = d / nu;
        float lbu = betav - alpha * mb;
        float q = vs * lbu * kdi;
        float udot = (-av - alpha * mm) + lbu;
        float nn2 = sc * sc * (vs * vs * nu2 + 2.f * vs * q * udot + q * q * ww);
        float nn = sqrtf(fmaxf(nn2, EPSV));
        float ch = coshf(nn), shn = sinhf(nn) / nn;
        float cxv = shn * sc * vs;
        float cmv = shn * sc * (q - vs * alpha);
        float cbv = ch + shn * sc * q;

        float cx[4], cm[4], cb[4];
#pragma unroll
        for (int k = 0; k < 4; k++) {
            cx[k] = __shfl_sync(0xffffffffu, cxv, k);
            cm[k] = __shfl_sync(0xffffffffu, cmv, k);
            cb[k] = __shfl_sync(0xffffffffu, cbv, k);
        }
#pragma unroll
        for (int k = 0; k < 4; k++) {
            float4 v = p4[l + 32 * k];
            float xr[4] = {v.x, v.y, v.z, v.w};
            float orr[4];
#pragma unroll
            for (int j = 0; j < 4; j++) {
                if (l == 0 && j < k) {
                    int i = 4 - k + j, n = k - 1 < 0 ? 0 : k - 1;
                    orr[j] = cx[n] * xr[j] + cm[n] * mu_e[i] + cb[n] * bm_e[i];
                } else {
                    int i = j - k + 3;
                    orr[j] = cx[k] * xr[j] + cm[k] * mu_r[i] + cb[k] * bm_r[i];
                }
            }
            __stcs(&o4[l + 32 * k], make_float4(orr[0], orr[1], orr[2], orr[3]));
        }
        if (l == 0) {
            float4 v = p4[128];
            float xr[4] = {v.x, v.y, v.z, v.w};
            float orr[4];
#pragma unroll
            for (int j = 0; j < 4; j++)
                orr[j] = cx[3] * xr[j] + cm[3] * mu_e[j] + cb[3] * bm_e[j];
            __stcs(&o4[128], make_float4(orr[0], orr[1], orr[2], orr[3]));
        }
    }
}

extern "C" void kernel_launch(void* const* d_in, const int* in_sizes, int n_in,
                              void* d_out, int out_size) {
    const float* x = (const float*)d_in[0];
    const float* bias = (const float*)d_in[1];
    const float* weight = (const float*)d_in[2];
    float* out = (float*)d_out;

    sum_kernel<<<dim3(8, BB), 516>>>(x);
    mu_kernel<<<65, 256>>>(bias);
    var_kernel<<<dim3(16, BB), 256>>>(x);
    scal_kernel<<<BB, 256>>>(weight);
    out_kernel<<<dim3(16, BB), 256>>>(x, out);
}

// round 5
// speedup vs baseline: 1.4903x; 1.0856x over previous
#include <cuda_runtime.h>

#define BB 64
#define NN 4096
#define FF 128
#define DD 129
#define EPSV 1e-7f

__device__ float g_spart[8 * BB * DD];
__device__ float g_mu[BB * DD];
__device__ float g_bm[DD];
__device__ float g_varsum[BB];
__device__ float4 g_bs[BB];        // (mb, mm, kdi, ww)

// Pass 1: partial sums over n. Grid (8, B), block 516.
__global__ void sum_kernel(const float* __restrict__ x) {
    __shared__ float sh[2064];
    int b = blockIdx.y, s = blockIdx.x, t = threadIdx.x;
    const float4* p = (const float4*)(x + (size_t)b * NN * DD + (size_t)s * 512 * DD);
    float a0 = 0.f, a1 = 0.f, a2 = 0.f, a3 = 0.f;
#pragma unroll 4
    for (int g = 0; g < 32; g++) {
        float4 v = p[(size_t)g * 516 + t];
        a0 += v.x; a1 += v.y; a2 += v.z; a3 += v.w;
    }
    sh[4 * t + 0] = a0; sh[4 * t + 1] = a1; sh[4 * t + 2] = a2; sh[4 * t + 3] = a3;
    __syncthreads();
    if (t < DD) {
        float acc = 0.f;
#pragma unroll
        for (int r = 0; r < 16; r++) acc += sh[t + DD * r];
        g_spart[(s * BB + b) * DD + t] = acc;
    }
}

__device__ __forceinline__ float block_reduce256(float v, float* sh) {
    int t = threadIdx.x;
    sh[t] = v;
    __syncthreads();
    for (int s = 128; s > 0; s >>= 1) {
        if (t < s) sh[t] += sh[t + s];
        __syncthreads();
    }
    float r = sh[0];
    __syncthreads();
    return r;
}

// Blocks 0..63: mu[b] + per-batch scalars (bm recomputed locally); zero varsum.
// Block 64: store bm.
__global__ void mu_kernel(const float* __restrict__ bias) {
    __shared__ float sh[256];
    int b = blockIdx.x, t = threadIdx.x;
    float bias_v = (t >= 1 && t < DD) ? bias[t - 1] : 0.f;
    float nb2 = block_reduce256(bias_v * bias_v, sh);
    float n = sqrtf(fmaxf(nb2, EPSV));
    float scl = sinhf(n) / n;
    float bmv = (t == 0) ? coshf(n) : ((t < DD) ? scl * bias_v : 0.f);
    if (b == BB) {
        if (t < DD) g_bm[t] = bmv;
        return;
    }
    float sv = 0.f;
    if (t < DD) {
#pragma unroll
        for (int s = 0; s < 8; s++) sv += g_spart[(s * BB + b) * DD + t];
    }
    float sgn = (t == 0) ? -1.f : 1.f;
    float r = block_reduce256(-sgn * sv * sv, sh);  // -ldot(s,s)
    float inv = rsqrtf(fmaxf(r, EPSV));
    float mv = sv * inv;
    if (t < DD) g_mu[b * DD + t] = mv;
    float mm = block_reduce256(sgn * mv * mv, sh);
    float mb = block_reduce256(sgn * mv * bmv, sh);
    float bb2 = block_reduce256(sgn * bmv * bmv, sh);
    if (t == 0) {
        g_varsum[b] = 0.f;
        g_bs[b] = make_float4(mb, mm, 1.f / (1.f - mb), mm + 2.f * mb + bb2);
    }
}

// Pass 2: varsum only. Grid (16, BB) REVERSED for L2 reuse of pass 1.
__global__ __launch_bounds__(256) void var_kernel(const float* __restrict__ x) {
    __shared__ float smu[DD];
    __shared__ float ssum;
    int t = threadIdx.x;
    int b = BB - 1 - blockIdx.y;
    int pbase = (15 - blockIdx.x) * 256;
    if (t < DD) smu[t] = g_mu[b * DD + t];
    if (t == 0) ssum = 0.f;
    __syncthreads();
    int w = t >> 5, l = t & 31;
    float mu_r[7], mu_e[4];
#pragma unroll
    for (int i = 0; i < 7; i++) {
        int c = 4 * l - 3 + i;
        mu_r[i] = (c >= 0) ? smu[c] : 0.f;
    }
#pragma unroll
    for (int i = 0; i < 4; i++) mu_e[i] = smu[125 + i];

    float vloc = 0.f;
    for (int g = w; g < 64; g += 8) {
        int n0 = pbase + g * 4;
        const float4* p4 = (const float4*)(x + ((size_t)b * NN + n0) * DD);
        float xr[4][4], xe[4];
#pragma unroll
        for (int k = 0; k < 4; k++) {
            float4 v = p4[l + 32 * k];
            xr[k][0] = v.x; xr[k][1] = v.y; xr[k][2] = v.z; xr[k][3] = v.w;
        }
        {
            float4 v = p4[128];
            xe[0] = v.x; xe[1] = v.y; xe[2] = v.z; xe[3] = v.w;
        }
        float pa[4] = {0, 0, 0, 0};
#pragma unroll
        for (int k = 0; k < 4; k++) {
#pragma unroll
            for (int j = 0; j < 4; j++) {
                float xv = xr[k][j];
                if (l == 0 && j < k) {
                    int i = 4 - k + j;
                    pa[k - 1 < 0 ? 0 : k - 1] -= mu_e[i] * xv;
                } else {
                    int c = 4 * l + j - k, i = j - k + 3;
                    float m = mu_r[i];
                    if (c == 0) pa[k] += m * xv;
                    else        pa[k] -= m * xv;
                }
            }
        }
        if (l == 0) {
#pragma unroll
            for (int j = 0; j < 4; j++) pa[3] -= mu_e[j] * xe[j];
        }
#pragma unroll
        for (int k = 0; k < 4; k++) {
#pragma unroll
            for (int o = 16; o > 0; o >>= 1)
                pa[k] += __shfl_xor_sync(0xffffffffu, pa[k], o);
        }
        if (l == 0) {
            float s = 0.f;
#pragma unroll
            for (int k = 0; k < 4; k++) {
                float alpha = fmaxf(pa[k], 1.f + EPSV);
                float d = acoshf(alpha);
                s += d * d;
            }
            vloc += s;
        }
    }
    if (l == 0) atomicAdd(&ssum, vloc);
    __syncthreads();
    if (t == 0) atomicAdd(&g_varsum[b], ssum);
}

// Pass 3: fully fused — recompute a/beta from x, coefficients, elementwise.
__global__ __launch_bounds__(256) void out_kernel(const float* __restrict__ x,
                                                  const float* __restrict__ weight,
                                                  float* __restrict__ out) {
    __shared__ float smu[DD], sbm[DD];
    __shared__ float4 sbs;
    __shared__ float ssc;
    int t = threadIdx.x;
    int b = blockIdx.y;
    int pbase = blockIdx.x * 256;
    if (t < DD) { smu[t] = g_mu[b * DD + t]; sbm[t] = g_bm[t]; }
    if (t == 0) {
        sbs = g_bs[b];
        float var = g_varsum[b] / (float)NN;
        ssc = sqrtf(weight[0] / (var + 1e-6f));
    }
    __syncthreads();
    float mb = sbs.x, mm = sbs.y, kdi = sbs.z, ww = sbs.w, sc = ssc;
    int w = t >> 5, l = t & 31;
    float mu_r[7], bm_r[7], mu_e[4], bm_e[4];
#pragma unroll
    for (int i = 0; i < 7; i++) {
        int c = 4 * l - 3 + i;
        mu_r[i] = (c >= 0) ? smu[c] : 0.f;
        bm_r[i] = (c >= 0) ? sbm[c] : 0.f;
    }
#pragma unroll
    for (int i = 0; i < 4; i++) { mu_e[i] = smu[125 + i]; bm_e[i] = sbm[125 + i]; }

    for (int g = w; g < 64; g += 8) {
        int n0 = pbase + g * 4;
        size_t base = ((size_t)b * NN + n0) * DD;
        const float4* p4 = (const float4*)(x + base);
        float4* o4 = (float4*)(out + base);

        float xr[4][4], xe[4];
#pragma unroll
        for (int k = 0; k < 4; k++) {
            float4 v = __ldcs(&p4[l + 32 * k]);
            xr[k][0] = v.x; xr[k][1] = v.y; xr[k][2] = v.z; xr[k][3] = v.w;
        }
        {
            float4 v = __ldcs(&p4[128]);
            xe[0] = v.x; xe[1] = v.y; xe[2] = v.z; xe[3] = v.w;
        }
        // a = -ldot(mu,x), beta = ldot(bm,x)
        float pa[4] = {0, 0, 0, 0}, pb[4] = {0, 0, 0, 0};
#pragma unroll
        for (int k = 0; k < 4; k++) {
#pragma unroll
            for (int j = 0; j < 4; j++) {
                float xv = xr[k][j];
                if (l == 0 && j < k) {
                    int i = 4 - k + j;
                    pa[k - 1 < 0 ? 0 : k - 1] -= mu_e[i] * xv;
                    pb[k - 1 < 0 ? 0 : k - 1] += bm_e[i] * xv;
                } else {
                    int c = 4 * l + j - k, i = j - k + 3;
                    float m = mu_r[i], bv = bm_r[i];
                    if (c == 0) { pa[k] += m * xv; pb[k] -= bv * xv; }
                    else        { pa[k] -= m * xv; pb[k] += bv * xv; }
                }
            }
        }
        if (l == 0) {
#pragma unroll
            for (int j = 0; j < 4; j++) { pa[3] -= mu_e[j] * xe[j]; pb[3] += bm_e[j] * xe[j]; }
        }
#pragma unroll
        for (int k = 0; k < 4; k++) {
#pragma unroll
            for (int o = 16; o > 0; o >>= 1) {
                pa[k] += __shfl_xor_sync(0xffffffffu, pa[k], o);
                pb[k] += __shfl_xor_sync(0xffffffffu, pb[k], o);
            }
        }
        // Lane l computes coefficients for point l&3, then broadcast.
        int li = l & 3;
        float av = pa[li], betav = pb[li];
        float alpha = fmaxf(av, 1.f + EPSV);
        float d = acoshf(alpha);
        float nu2 = 2.f * alpha * av - alpha * alpha - 1.f;
        float nu = sqrtf(fmaxf(nu2, EPSV));
        float vs = d / nu;
        float lbu = betav - alpha * mb;
        float q = vs * lbu * kdi;
        float udot = (-av - alpha * mm) + lbu;
        float nn2 = sc * sc * (vs * vs * nu2 + 2.f * vs * q * udot + q * q * ww);
        float nn = sqrtf(fmaxf(nn2, EPSV));
        float ch = coshf(nn), shn = sinhf(nn) / nn;
        float cxv = shn * sc * vs;
        float cmv = shn * sc * (q - vs * alpha);
        float cbv = ch + shn * sc * q;

        float cx[4], cm[4], cb[4];
#pragma unroll
        for (int k = 0; k < 4; k++) {
            cx[k] = __shfl_sync(0xffffffffu, cxv, k);
            cm[k] = __shfl_sync(0xffffffffu, cmv, k);
            cb[k] = __shfl_sync(0xffffffffu, cbv, k);
        }
#pragma unroll
        for (int k = 0; k < 4; k++) {
            float orr[4];
#pragma unroll
            for (int j = 0; j < 4; j++) {
                if (l == 0 && j < k) {
                    int i = 4 - k + j, n = k - 1 < 0 ? 0 : k - 1;
                    orr[j] = cx[n] * xr[k][j] + cm[n] * mu_e[i] + cb[n] * bm_e[i];
                } else {
                    int i = j - k + 3;
                    orr[j] = cx[k] * xr[k][j] + cm[k] * mu_r[i] + cb[k] * bm_r[i];
                }
            }
            __stcs(&o4[l + 32 * k], make_float4(orr[0], orr[1], orr[2], orr[3]));
        }
        if (l == 0) {
            float orr[4];
#pragma unroll
            for (int j = 0; j < 4; j++)
                orr[j] = cx[3] * xe[j] + cm[3] * mu_e[j] + cb[3] * bm_e[j];
            __stcs(&o4[128], make_float4(orr[0], orr[1], orr[2], orr[3]));
        }
    }
}

extern "C" void kernel_launch(void* const* d_in, const int* in_sizes, int n_in,
                              void* d_out, int out_size) {
    const float* x = (const float*)d_in[0];
    const float* bias = (const float*)d_in[1];
    const float* weight = (const float*)d_in[2];
    float* out = (float*)d_out;

    sum_kernel<<<dim3(8, BB), 516>>>(x);
    mu_kernel<<<65, 256>>>(bias);
    var_kernel<<<dim3(16, BB), 256>>>(x);
    out_kernel<<<dim3(16, BB), 256>>>(x, weight, out);
}

// round 7
// speedup vs baseline: 1.5525x; 1.0418x over previous
#include <cuda_runtime.h>

#define BB 64
#define NN 4096
#define DD 129
#define EPSV 1e-7f
#define HALF 2048

__device__ float g_spart[BB * 2 * DD];
__device__ float g_varpart[BB * 2];
__device__ int g_cnt1[BB];
__device__ int g_cnt2[BB];

__global__ void init_kernel() {
    int t = threadIdx.x;
    if (t < BB) { g_cnt1[t] = 0; g_cnt2[t] = 0; }
}

__device__ __forceinline__ float block_reduce1024(float v, float* sh) {
    int t = threadIdx.x;
    sh[t] = v;
    __syncthreads();
    for (int s = 512; s > 0; s >>= 1) {
        if (t < s) sh[t] += sh[t + s];
        __syncthreads();
    }
    float r = sh[0];
    __syncthreads();
    return r;
}

__global__ __launch_bounds__(1024, 1) void fused_kernel(
    const float* __restrict__ x, const float* __restrict__ bias,
    const float* __restrict__ weight, float* __restrict__ out) {
    // sbuf: phase1 = 32-warp partial sums (32*129); reduces = first 1024;
    //       phase2/3 = (a,beta) cache for 2048 points (4096 floats).
    __shared__ float sbuf[4128];
    __shared__ float smu[DD], sbm[DD];
    __shared__ float sVar[32];
    __shared__ float sScal;

    int tid = threadIdx.x, w = tid >> 5, l = tid & 31;
    int b = blockIdx.x >> 1, h = blockIdx.x & 1;
    const float* xb = x + ((size_t)b * NN + (size_t)h * HALF) * DD;
    float* ob = out + ((size_t)b * NN + (size_t)h * HALF) * DD;

    // bias point on manifold
    float bias_v = (tid >= 1 && tid < DD) ? bias[tid - 1] : 0.f;
    float nb2 = block_reduce1024(bias_v * bias_v, sbuf);
    float nb = sqrtf(fmaxf(nb2, EPSV));
    float sclb = sinhf(nb) / nb;
    float bmv = (tid == 0) ? coshf(nb) : ((tid < DD) ? sclb * bias_v : 0.f);
    if (tid < DD) sbm[tid] = bmv;
    float sgn = (tid == 0) ? -1.f : 1.f;
    float bmr = (tid < DD) ? bmv : 0.f;
    float bb2 = block_reduce1024(sgn * bmr * bmr, sbuf);  // ldot(bm,bm)

    // ---------------- Phase 1: partial sum over this block's 2048 points -----
    for (int i = tid; i < 4128; i += 1024) sbuf[i] = 0.f;
    __syncthreads();
    {
        float acc_r[7] = {0, 0, 0, 0, 0, 0, 0};
        float acc_e[4] = {0, 0, 0, 0};
        for (int m = 0; m < 16; m++) {
            int g = w + 32 * m;
            const float4* p4 = (const float4*)(xb + (size_t)g * 4 * DD);
            float4 v[4];
#pragma unroll
            for (int k = 0; k < 4; k++) v[k] = p4[l + 32 * k];
            float4 ve = p4[128];
#pragma unroll
            for (int k = 0; k < 4; k++) {
                float xr0[4] = {v[k].x, v[k].y, v[k].z, v[k].w};
#pragma unroll
                for (int j = 0; j < 4; j++) {
                    if (l == 0 && j < k) acc_e[4 - k + j] += xr0[j];
                    else acc_r[j - k + 3] += xr0[j];
                }
            }
            if (l == 0) {
                acc_e[0] += ve.x; acc_e[1] += ve.y;
                acc_e[2] += ve.z; acc_e[3] += ve.w;
            }
        }
#pragma unroll
        for (int i = 0; i < 7; i++) {
            int c = 4 * l - 3 + i;
            if (c >= 0) sbuf[w * DD + c] += acc_r[i];
            __syncwarp();
        }
        if (l == 0) {
#pragma unroll
            for (int i = 0; i < 4; i++) sbuf[w * DD + 125 + i] += acc_e[i];
        }
    }
    __syncthreads();
    if (tid < DD) {
        float s = 0.f;
#pragma unroll
        for (int w2 = 0; w2 < 32; w2++) s += sbuf[w2 * DD + tid];
        g_spart[(b * 2 + h) * DD + tid] = s;
    }
    __threadfence();
    __syncthreads();
    if (tid == 0) {
        atomicAdd(&g_cnt1[b], 1);
        while (atomicAdd(&g_cnt1[b], 0) < 2) __nanosleep(32);
        __threadfence();
    }
    __syncthreads();

    // ---------------- mu + per-batch Lorentz scalars --------------------------
    float sv = 0.f;
    if (tid < DD)
        sv = __ldcg(&g_spart[(b * 2 + 0) * DD + tid]) +
             __ldcg(&g_spart[(b * 2 + 1) * DD + tid]);
    float r = block_reduce1024(-sgn * sv * sv, sbuf);  // -ldot(s,s)
    float inv = rsqrtf(fmaxf(r, EPSV));
    float mv = sv * inv;
    if (tid < DD) smu[tid] = mv;
    float lmm = block_reduce1024(sgn * mv * mv, sbuf);   // ldot(mu,mu)
    float lmb = block_reduce1024(sgn * mv * bmr, sbuf);  // ldot(mu,bm)
    float lkdi = 1.f / (1.f - lmb);
    float lww = lmm + 2.f * lmb + bb2;

    float mu_r[7], bm_r[7], mu_e[4], bm_e[4];
#pragma unroll
    for (int i = 0; i < 7; i++) {
        int c = 4 * l - 3 + i;
        mu_r[i] = (c >= 0) ? smu[c] : 0.f;
        bm_r[i] = (c >= 0) ? sbm[c] : 0.f;
    }
#pragma unroll
    for (int i = 0; i < 4; i++) { mu_e[i] = smu[125 + i]; bm_e[i] = sbm[125 + i]; }

    // ---------------- Phase 2: a,beta per point (cache in SMEM) + varsum ------
    float vloc = 0.f;
    for (int m = 0; m < 16; m++) {
        int g = w + 32 * m;
        const float4* p4 = (const float4*)(xb + (size_t)g * 4 * DD);
        float4 v[4];
#pragma unroll
        for (int k = 0; k < 4; k++) v[k] = p4[l + 32 * k];
        float4 ve = p4[128];
        float pa[4] = {0, 0, 0, 0}, pb[4] = {0, 0, 0, 0};
#pragma unroll
        for (int k = 0; k < 4; k++) {
            float xr0[4] = {v[k].x, v[k].y, v[k].z, v[k].w};
#pragma unroll
            for (int j = 0; j < 4; j++) {
                float xv = xr0[j];
                if (l == 0 && j < k) {
                    int i = 4 - k + j, nidx = k - 1;
                    pa[nidx] -= mu_e[i] * xv;
                    pb[nidx] += bm_e[i] * xv;
                } else {
                    int c = 4 * l + j - k, i = j - k + 3;
                    float m2 = mu_r[i], bv2 = bm_r[i];
                    if (c == 0) { pa[k] += m2 * xv; pb[k] -= bv2 * xv; }
                    else        { pa[k] -= m2 * xv; pb[k] += bv2 * xv; }
                }
            }
        }
        if (l == 0) {
            pa[3] -= mu_e[0] * ve.x + mu_e[1] * ve.y + mu_e[2] * ve.z + mu_e[3] * ve.w;
            pb[3] += bm_e[0] * ve.x + bm_e[1] * ve.y + bm_e[2] * ve.z + bm_e[3] * ve.w;
        }
#pragma unroll
        for (int k = 0; k < 4; k++) {
#pragma unroll
            for (int o = 16; o > 0; o >>= 1) {
                pa[k] += __shfl_xor_sync(0xffffffffu, pa[k], o);
                pb[k] += __shfl_xor_sync(0xffffffffu, pb[k], o);
            }
        }
        if (l == 0) {
            float4* s4 = (float4*)sbuf;
            s4[2 * g] = make_float4(pa[0], pb[0], pa[1], pb[1]);
            s4[2 * g + 1] = make_float4(pa[2], pb[2], pa[3], pb[3]);
#pragma unroll
            for (int k = 0; k < 4; k++) {
                float alpha = fmaxf(pa[k], 1.f + EPSV);
                float d = acoshf(alpha);
                vloc += d * d;
            }
        }
    }
    if (l == 0) sVar[w] = vloc;
    __syncthreads();
    if (tid == 0) {
        float s = 0.f;
#pragma unroll
        for (int w3 = 0; w3 < 32; w3++) s += sVar[w3];
        g_varpart[b * 2 + h] = s;
        __threadfence();
        atomicAdd(&g_cnt2[b], 1);
        while (atomicAdd(&g_cnt2[b], 0) < 2) __nanosleep(32);
        __threadfence();
        float vs = __ldcg(&g_varpart[b * 2]) + __ldcg(&g_varpart[b * 2 + 1]);
        float var = vs / (float)NN;
        sScal = sqrtf(weight[0] / (var + 1e-6f));
    }
    __syncthreads();
    float sc = sScal;

    // ---------------- Phase 3: coefficients from cache + elementwise ----------
    for (int m = 0; m < 16; m++) {
        int g = w + 32 * m;
        const float4* p4 = (const float4*)(xb + (size_t)g * 4 * DD);
        float4* o4 = (float4*)(ob + (size_t)g * 4 * DD);
        float xr[4][4], xe[4];
#pragma unroll
        for (int k = 0; k < 4; k++) {
            float4 v = __ldcs(&p4[l + 32 * k]);
            xr[k][0] = v.x; xr[k][1] = v.y; xr[k][2] = v.z; xr[k][3] = v.w;
        }
        {
            float4 v = __ldcs(&p4[128]);
            xe[0] = v.x; xe[1] = v.y; xe[2] = v.z; xe[3] = v.w;
        }
        int li = l & 3;
        float2 ab = ((float2*)sbuf)[4 * g + li];
        float av = ab.x, betav = ab.y;
        float alpha = fmaxf(av, 1.f + EPSV);
        float d = acoshf(alpha);
        float nu2 = 2.f * alpha * av - alpha * alpha - 1.f;
        float nu = sqrtf(fmaxf(nu2, EPSV));
        float vsr = d / nu;
        float lbu = betav - alpha * lmb;
        float q = vsr * lbu * lkdi;
        float udot = (-av - alpha * lmm) + lbu;
        float nn2 = sc * sc * (vsr * vsr * nu2 + 2.f * vsr * q * udot + q * q * lww);
        float nnv = sqrtf(fmaxf(nn2, EPSV));
        float chv = coshf(nnv), shnv = sinhf(nnv) / nnv;
        float cxv = shnv * sc * vsr;
        float cmv = shnv * sc * (q - vsr * alpha);
        float cbv = chv + shnv * sc * q;

        float cx[4], cm[4], cb[4];
#pragma unroll
        for (int k = 0; k < 4; k++) {
            cx[k] = __shfl_sync(0xffffffffu, cxv, k);
            cm[k] = __shfl_sync(0xffffffffu, cmv, k);
            cb[k] = __shfl_sync(0xffffffffu, cbv, k);
        }
#pragma unroll
        for (int k = 0; k < 4; k++) {
            float orr[4];
#pragma unroll
            for (int j = 0; j < 4; j++) {
                if (l == 0 && j < k) {
                    int i = 4 - k + j, n = k - 1;
                    orr[j] = cx[n] * xr[k][j] + cm[n] * mu_e[i] + cb[n] * bm_e[i];
                } else {
                    int i = j - k + 3;
                    orr[j] = cx[k] * xr[k][j] + cm[k] * mu_r[i] + cb[k] * bm_r[i];
                }
            }
            __stcs(&o4[l + 32 * k], make_float4(orr[0], orr[1], orr[2], orr[3]));
        }
        if (l == 0) {
            float orr[4];
#pragma unroll
            for (int j = 0; j < 4; j++)
                orr[j] = cx[3] * xe[j] + cm[3] * mu_e[j] + cb[3] * bm_e[j];
            __stcs(&o4[128], make_float4(orr[0], orr[1], orr[2], orr[3]));
        }
    }
}

extern "C" void kernel_launch(void* const* d_in, const int* in_sizes, int n_in,
                              void* d_out, int out_size) {
    const float* x = (const float*)d_in[0];
    const float* bias = (const float*)d_in[1];
    const float* weight = (const float*)d_in[2];
    float* out = (float*)d_out;

    init_kernel<<<1, 128>>>();
    fused_kernel<<<128, 1024>>>(x, bias, weight, out);
}